// round 13
// baseline (speedup 1.0000x reference)
#include <cuda_runtime.h>
#include <string.h>

// Problem constants
namespace {
constexpr int B_  = 4;
constexpr int C_  = 128;
constexpr int N_  = 1024;
constexpr int KNN = 20;
constexpr int M_  = 4096;   // N*UP
constexpr int OC  = 512;    // edge-conv out channels
constexpr int CH  = 130;    // net channels after grid concat
constexpr int CF  = 32;     // f/g channels
constexpr int MID = 256;    // W1 out
constexpr int RO  = 128;    // W2 out
constexpr int JS  = 2;      // j-splits for ogemm
}
#define EPS_ 1e-5f
#define NEGINF_ -3.4e38f

// ---- packed f32x2 FMA with defined-behavior punning ----
__device__ __forceinline__ float2 ffma2(float2 a, float2 b, float2 c) {
    unsigned long long au, bu, cu, du;
    memcpy(&au, &a, 8);
    memcpy(&bu, &b, 8);
    memcpy(&cu, &c, 8);
    asm("fma.rn.f32x2 %0, %1, %2, %3;" : "=l"(du) : "l"(au), "l"(bu), "l"(cu));
    float2 d;
    memcpy(&d, &du, 8);
    return d;
}
__device__ __forceinline__ float2 pack2(float x) { return make_float2(x, x); }

// ---- scratch (device globals; no allocations allowed) ----
__device__ float d_sq   [B_*N_];
__device__ float d_negd [B_*N_*N_];
__device__ int   d_idx  [B_*N_*KNN];
__device__ float d_Yt   [B_*N_*OC];    // [b][n][o]
__device__ float d_baset[B_*N_*OC];    // [b][n][o]
__device__ float d_st1p [2*256*OC];    // per-block partial sums (deterministic)
__device__ float d_st1  [2*OC];        // finalized: sc[o], sh[o]
__device__ float d_net3 [B_*CH*M_];    // [b][c][m]
__device__ float d_fr   [B_*CF*M_];
__device__ float d_gr   [B_*CF*M_];
__device__ float d_hr   [B_*CH*M_];
__device__ float d_st2  [2*(CF+CF+CH)];
__device__ float d_fn   [B_*CF*M_];
__device__ float d_gn   [B_*CF*M_];
__device__ float d_hn   [B_*CH*M_];    // h normalized * gamma/Z (fused)
__device__ float d_s    [(size_t)B_*M_*M_];   // raw attention scores (never normalized)
__device__ float d_mx   [B_*M_];              // per-row max
__device__ float d_wj   [B_*M_];              // gamma / Z per row
__device__ float d_op   [(size_t)JS*B_*CH*M_]; // ogemm partials
__device__ float d_n4   [B_*CH*M_];
__device__ float d_y1   [B_*MID*M_];

// ---------------- 1) per-point squared norms ----------------
__global__ void k_sq(const float* __restrict__ x) {
    int t = blockIdx.x * 256 + threadIdx.x;      // B*N = 4096
    int b = t >> 10, n = t & 1023;
    const float* xb = x + b * C_ * N_ + n;
    float s = 0.f;
#pragma unroll 8
    for (int c = 0; c < C_; c++) { float v = xb[c * N_]; s = fmaf(v, v, s); }
    d_sq[t] = s;
}

// ---------------- 2) neg squared distance: 2 x^T x - sq_n - sq_m ----------------
__global__ void k_negd(const float* __restrict__ x) {
    int b = blockIdx.z;
    int n0 = blockIdx.y * 64, m0 = blockIdx.x * 64;
    __shared__ float As[32][64];
    __shared__ float Bs[32][64];
    int tid = threadIdx.x;
    const float* xb = x + b * C_ * N_;
    float2 acc[4][2] = {};
    for (int k0 = 0; k0 < C_; k0 += 32) {
        for (int e = tid; e < 32 * 64; e += 256) {
            int k = e >> 6, i = e & 63;
            As[k][i] = xb[(k0 + k) * N_ + n0 + i];
            Bs[k][i] = xb[(k0 + k) * N_ + m0 + i];
        }
        __syncthreads();
        int ty = tid >> 4, tx = tid & 15;
#pragma unroll
        for (int k = 0; k < 32; k++) {
            float2 b0 = *(const float2*)&Bs[k][tx * 4];
            float2 b1 = *(const float2*)&Bs[k][tx * 4 + 2];
#pragma unroll
            for (int i = 0; i < 4; i++) {
                float2 av = pack2(As[k][ty * 4 + i]);
                acc[i][0] = ffma2(av, b0, acc[i][0]);
                acc[i][1] = ffma2(av, b1, acc[i][1]);
            }
        }
        __syncthreads();
    }
    int ty = tid >> 4, tx = tid & 15;
#pragma unroll
    for (int i = 0; i < 4; i++) {
        int n = n0 + ty * 4 + i;
        float sn = d_sq[b * N_ + n];
        float4 o;
        o.x = 2.f * acc[i][0].x - sn - d_sq[b * N_ + m0 + tx * 4 + 0];
        o.y = 2.f * acc[i][0].y - sn - d_sq[b * N_ + m0 + tx * 4 + 1];
        o.z = 2.f * acc[i][1].x - sn - d_sq[b * N_ + m0 + tx * 4 + 2];
        o.w = 2.f * acc[i][1].y - sn - d_sq[b * N_ + m0 + tx * 4 + 3];
        *(float4*)&d_negd[(b * N_ + n) * N_ + m0 + tx * 4] = o;
    }
}

// ---------------- 3) top-k (k=20), warp per row, tie -> lower index ----------------
__global__ void k_topk() {
    int row = blockIdx.x * 8 + (threadIdx.x >> 5);    // 4096 rows
    int lane = threadIdx.x & 31;
    const float* src = &d_negd[(size_t)row * N_];
    float v[32];
#pragma unroll
    for (int i = 0; i < 32; i++) v[i] = src[lane + i * 32];
    for (int t = 0; t < KNN; t++) {
        float bv = v[0]; int bi = lane;
#pragma unroll
        for (int i = 1; i < 32; i++) {
            int gi = i * 32 + lane;
            float vv = v[i];
            if (vv > bv || (vv == bv && gi < bi)) { bv = vv; bi = gi; }
        }
#pragma unroll
        for (int off = 16; off > 0; off >>= 1) {
            float ov = __shfl_down_sync(0xffffffff, bv, off);
            int   oi = __shfl_down_sync(0xffffffff, bi, off);
            if (ov > bv || (ov == bv && oi < bi)) { bv = ov; bi = oi; }
        }
        bi = __shfl_sync(0xffffffff, bi, 0);
        if (lane == 0) d_idx[row * KNN + t] = bi;
        int slot = bi >> 5;
        bool mine = (bi & 31) == lane;
#pragma unroll
        for (int i = 0; i < 32; i++) if (i == slot && mine) v[i] = NEGINF_;
    }
}

// ---------------- 4) Y = Wa@x, base = (Wb-Wa)@x, both point-major (coalesced Wec) ----------------
__global__ void k_yb(const float* __restrict__ x, const float* __restrict__ Wec) {
    int b = blockIdx.z;
    int n0 = blockIdx.y * 64;   // 16
    int o0 = blockIdx.x * 64;   // 8
    __shared__ float Xs[32][66];
    __shared__ float Was[32][66];
    __shared__ float Wbs[32][66];
    int tid = threadIdx.x;
    float2 a1[4][2] = {}, a2[4][2] = {};
    for (int k0 = 0; k0 < C_; k0 += 32) {
        for (int e = tid; e < 32 * 64; e += 256) {
            int k = e >> 6, i = e & 63;
            Xs[k][i] = x[b * C_ * N_ + (k0 + k) * N_ + n0 + i];
        }
        for (int e = tid; e < 64 * 32; e += 256) {
            int i = e >> 5, k = e & 31;
            float wa = Wec[(o0 + i) * 256 + k0 + k];
            float wb = Wec[(o0 + i) * 256 + 128 + k0 + k];
            Was[k][i] = wa;
            Wbs[k][i] = wb - wa;
        }
        __syncthreads();
        int ty = tid >> 4, tx = tid & 15;   // ty -> n, tx -> o
#pragma unroll
        for (int k = 0; k < 32; k++) {
            float2 wa0 = *(const float2*)&Was[k][tx * 4];
            float2 wa1 = *(const float2*)&Was[k][tx * 4 + 2];
            float2 wb0 = *(const float2*)&Wbs[k][tx * 4];
            float2 wb1 = *(const float2*)&Wbs[k][tx * 4 + 2];
#pragma unroll
            for (int i = 0; i < 4; i++) {
                float2 xv = pack2(Xs[k][ty * 4 + i]);
                a1[i][0] = ffma2(xv, wa0, a1[i][0]);
                a1[i][1] = ffma2(xv, wa1, a1[i][1]);
                a2[i][0] = ffma2(xv, wb0, a2[i][0]);
                a2[i][1] = ffma2(xv, wb1, a2[i][1]);
            }
        }
        __syncthreads();
    }
    int ty = tid >> 4, tx = tid & 15;
#pragma unroll
    for (int i = 0; i < 4; i++) {
        int n = n0 + ty * 4 + i;
        *(float4*)&d_Yt   [(b * N_ + n) * OC + o0 + tx * 4] =
            make_float4(a1[i][0].x, a1[i][0].y, a1[i][1].x, a1[i][1].y);
        *(float4*)&d_baset[(b * N_ + n) * OC + o0 + tx * 4] =
            make_float4(a2[i][0].x, a2[i][0].y, a2[i][1].x, a2[i][1].y);
    }
}

// ---------------- 5) BN stats for edge-conv (deterministic partials, 256 blocks) ----------------
__global__ void k_stats1() {
    int b = blockIdx.y;
    int nc = blockIdx.x;            // 64 chunks of 16 points
    int p = b * 64 + nc;
    int o = threadIdx.x;            // 512
    __shared__ int sidx[16 * KNN];
    for (int e = threadIdx.x; e < 16 * KNN; e += 512)
        sidx[e] = d_idx[(b * N_ + nc * 16) * KNN + e];
    __syncthreads();
    float s = 0.f, ss = 0.f;
    for (int nn = 0; nn < 16; nn++) {
        int n = nc * 16 + nn;
        float bv = d_baset[(b * N_ + n) * OC + o];
#pragma unroll
        for (int k = 0; k < KNN; k++) {
            int j = sidx[nn * KNN + k];
            float v = d_Yt[(b * N_ + j) * OC + o] + bv;
            s += v; ss = fmaf(v, v, ss);
        }
    }
    d_st1p[p * OC + o] = s;
    d_st1p[(256 + p) * OC + o] = ss;
}

// reduce partials AND finalize BN scale/shift: d_st1[o]=sc, d_st1[OC+o]=sh
__global__ void k_red1(const float* __restrict__ g_ec, const float* __restrict__ b_ec) {
    int o = blockIdx.x * 256 + threadIdx.x;
    if (o >= OC) return;
    float s = 0.f, ss = 0.f;
    for (int p = 0; p < 256; p++) { s += d_st1p[p * OC + o]; ss += d_st1p[(256 + p) * OC + o]; }
    const float cnt = (float)(B_ * N_ * KNN);
    float mean = s / cnt;
    float var  = ss / cnt - mean * mean;
    float sc = rsqrtf(var + EPS_) * g_ec[o];
    d_st1[o] = sc;
    d_st1[OC + o] = b_ec[o] - mean * sc;
}

// ---------------- 6) normalize + leaky + max over k, write reshaped net3 ----------------
__global__ void k_edgemax() {
    int bn = blockIdx.x;
    int b = bn >> 10, n = bn & 1023;
    __shared__ int sidx[KNN];
    int tid = threadIdx.x;
    if (tid < KNN) sidx[tid] = d_idx[bn * KNN + tid];
    __syncthreads();
    for (int o = tid; o < OC; o += 256) {
        float sc = d_st1[o];
        float sh = d_st1[OC + o];
        float bv = d_baset[bn * OC + o];
        float best = NEGINF_;
#pragma unroll
        for (int k = 0; k < KNN; k++) {
            float v = d_Yt[(b * N_ + sidx[k]) * OC + o] + bv;
            v = fmaf(v, sc, sh);
            v = v > 0.f ? v : 0.2f * v;
            best = fmaxf(best, v);
        }
        int u = o >> 7, c = o & 127;
        d_net3[(b * CH + c) * M_ + n * 4 + u] = best;
    }
}

__global__ void k_grid() {
    int t = blockIdx.x * 256 + threadIdx.x;   // B*M = 16384
    int b = t >> 12, m = t & 4095;
    int gi = m >> 10;
    float gx = (gi < 2) ? -0.2f : 0.2f;
    float gy = (gi & 1) ? 0.2f : -0.2f;
    d_net3[(b * CH + 128) * M_ + m] = gx;
    d_net3[(b * CH + 129) * M_ + m] = gy;
}

// ---------------- 7) f/g/h raw convs (K=130), q-split row assignment ----------------
__global__ void k_fgh(const float* __restrict__ Wf, const float* __restrict__ bf,
                      const float* __restrict__ Wg, const float* __restrict__ bg,
                      const float* __restrict__ Wh, const float* __restrict__ bh) {
    int b = blockIdx.y, m0 = blockIdx.x * 64, half = blockIdx.z;
    __shared__ float In[CH][64];
    int tid = threadIdx.x;
    for (int e = tid; e < CH * 64; e += 256) {
        int k = e >> 6, i = e & 63;
        In[k][i] = d_net3[(b * CH + k) * M_ + m0 + i];
    }
    __syncthreads();
    int mi = tid & 15, ri = tid >> 4;
    int rbase = half * 112 + ri;
    const float* wp[7]; float bs_[7]; float* op[7]; bool val[7];
#pragma unroll
    for (int q = 0; q < 7; q++) {
        int r = rbase + 16 * q;
        val[q] = (r < 194);
        if (!val[q]) { wp[q] = Wf; bs_[q] = 0.f; op[q] = d_fr; continue; }
        if (r < 32)      { wp[q] = Wf + r * CH;          bs_[q] = bf[r];      op[q] = &d_fr[(b * CF + r) * M_]; }
        else if (r < 64) { int c = r - 32; wp[q] = Wg + c * CH; bs_[q] = bg[c]; op[q] = &d_gr[(b * CF + c) * M_]; }
        else             { int c = r - 64; wp[q] = Wh + c * CH; bs_[q] = bh[c]; op[q] = &d_hr[(b * CH + c) * M_]; }
    }
    float acc[7][4] = {};
#pragma unroll 2
    for (int k = 0; k < CH; k++) {
        float4 iv = *(const float4*)&In[k][mi * 4];
#pragma unroll
        for (int q = 0; q < 7; q++) {
            float w = wp[q][k];
            acc[q][0] = fmaf(w, iv.x, acc[q][0]);
            acc[q][1] = fmaf(w, iv.y, acc[q][1]);
            acc[q][2] = fmaf(w, iv.z, acc[q][2]);
            acc[q][3] = fmaf(w, iv.w, acc[q][3]);
        }
    }
#pragma unroll
    for (int q = 0; q < 7; q++) {
        if (val[q]) {
            float bv = bs_[q];
            *(float4*)&op[q][m0 + mi * 4] =
                make_float4(acc[q][0] + bv, acc[q][1] + bv, acc[q][2] + bv, acc[q][3] + bv);
        }
    }
}

// ---------------- 8) BN stats for f/g/h (one block per channel) ----------------
__global__ void k_stats2() {
    int ch = blockIdx.x, tid = threadIdx.x;   // 194 channels
    __shared__ float r1[256], r2[256];
    float s = 0.f, ss = 0.f;
    for (int b = 0; b < B_; b++) {
        const float* p;
        if (ch < 32)      p = &d_fr[(b * CF + ch) * M_];
        else if (ch < 64) p = &d_gr[(b * CF + (ch - 32)) * M_];
        else              p = &d_hr[(b * CH + (ch - 64)) * M_];
        for (int m = tid; m < M_; m += 256) { float v = p[m]; s += v; ss = fmaf(v, v, ss); }
    }
    r1[tid] = s; r2[tid] = ss;
    __syncthreads();
    for (int st = 128; st > 0; st >>= 1) {
        if (tid < st) { r1[tid] += r1[tid + st]; r2[tid] += r2[tid + st]; }
        __syncthreads();
    }
    if (tid == 0) { d_st2[ch] = r1[0]; d_st2[194 + ch] = r2[0]; }
}

// ---------------- 9) normalize + relu for f (sel 0) and g (sel 1) ----------------
__global__ void k_norm2(int sel, const float* __restrict__ gamma, const float* __restrict__ beta) {
    int t = blockIdx.x * 256 + threadIdx.x;
    if (t >= B_ * CF * M_) return;
    int c = (t / M_) % CF;
    int off = (sel == 0) ? 0 : 32;
    const float cntf = (float)(B_ * M_);
    float mean = d_st2[off + c] / cntf;
    float var  = d_st2[194 + off + c] / cntf - mean * mean;
    float sc = rsqrtf(var + EPS_) * gamma[c];
    float sh = beta[c] - mean * sc;
    const float* raw = (sel == 0) ? d_fr : d_gr;
    float* outp      = (sel == 0) ? d_fn : d_gn;
    outp[t] = fmaxf(fmaf(raw[t], sc, sh), 0.f);
}

// ---------------- 9b) h: normalize + relu + fold gamma/Z (fused) ----------------
__global__ void k_norm2h(const float* __restrict__ gamma, const float* __restrict__ beta) {
    int t = blockIdx.x * 256 + threadIdx.x;
    if (t >= B_ * CH * M_) return;
    int c = (t / M_) % CH;
    int m = t % M_;
    int b = t / (CH * M_);
    const float cntf = (float)(B_ * M_);
    float mean = d_st2[64 + c] / cntf;
    float var  = d_st2[194 + 64 + c] / cntf - mean * mean;
    float sc = rsqrtf(var + EPS_) * gamma[c];
    float sh = beta[c] - mean * sc;
    d_hn[t] = fmaxf(fmaf(d_hr[t], sc, sh), 0.f) * d_wj[b * M_ + m];
}

// ---------------- 10) s[b,m,n] = sum_c g[c,m] f[c,n]  (K=32, 64m x 128n tiles) ----------------
__global__ void k_sgemm() {
    int b = blockIdx.z;
    int m0 = blockIdx.y * 64, n0 = blockIdx.x * 128;
    __shared__ float Gs[CF][64];
    __shared__ float Fs[CF][128];
    int tid = threadIdx.x;
    for (int e = tid; e < CF * 64; e += 256) {
        int k = e >> 6, i = e & 63;
        Gs[k][i] = d_gn[(b * CF + k) * M_ + m0 + i];
    }
    for (int e = tid; e < CF * 128; e += 256) {
        int k = e >> 7, i = e & 127;
        Fs[k][i] = d_fn[(b * CF + k) * M_ + n0 + i];
    }
    __syncthreads();
    int ty = tid >> 4, tx = tid & 15;   // ty -> m group (4), tx -> n group (8)
    float2 acc[4][4] = {};
#pragma unroll
    for (int k = 0; k < CF; k++) {
        float4 gv = *(const float4*)&Gs[k][ty * 4];
        float4 fa = *(const float4*)&Fs[k][tx * 8];
        float4 fb = *(const float4*)&Fs[k][tx * 8 + 4];
        float gm[4] = {gv.x, gv.y, gv.z, gv.w};
        float2 fn0 = make_float2(fa.x, fa.y), fn1 = make_float2(fa.z, fa.w);
        float2 fn2 = make_float2(fb.x, fb.y), fn3 = make_float2(fb.z, fb.w);
#pragma unroll
        for (int i = 0; i < 4; i++) {
            float2 gp = pack2(gm[i]);
            acc[i][0] = ffma2(gp, fn0, acc[i][0]);
            acc[i][1] = ffma2(gp, fn1, acc[i][1]);
            acc[i][2] = ffma2(gp, fn2, acc[i][2]);
            acc[i][3] = ffma2(gp, fn3, acc[i][3]);
        }
    }
#pragma unroll
    for (int i = 0; i < 4; i++) {
        int m = m0 + ty * 4 + i;
        float* dst = &d_s[((size_t)(b * M_ + m)) * M_ + n0 + tx * 8];
        *(float4*)&dst[0] = make_float4(acc[i][0].x, acc[i][0].y, acc[i][1].x, acc[i][1].y);
        *(float4*)&dst[4] = make_float4(acc[i][2].x, acc[i][2].y, acc[i][3].x, acc[i][3].y);
    }
}

// ---------------- 11) row stats: mx, wj = gamma/Z (256 threads, R10-proven) ----------------
__global__ void k_rowstats(const float* __restrict__ gam) {
    int bm = blockIdx.x;     // B*M rows
    __shared__ float row[M_];
    __shared__ float red[256];
    const float* src = &d_s[(size_t)bm * M_];
    int tid = threadIdx.x;
    float mx = NEGINF_;
    for (int i = tid * 4; i < M_; i += 1024) {
        float4 v = *(const float4*)&src[i];
        *(float4*)&row[i] = v;
        mx = fmaxf(mx, fmaxf(fmaxf(v.x, v.y), fmaxf(v.z, v.w)));
    }
    red[tid] = mx;
    __syncthreads();
    for (int s = 128; s > 0; s >>= 1) { if (tid < s) red[tid] = fmaxf(red[tid], red[tid + s]); __syncthreads(); }
    mx = red[0];
    __syncthreads();
    float sum = 0.f;
    for (int i = tid * 4; i < M_; i += 1024) {
        float4 v = *(const float4*)&row[i];
        sum += (__expf(v.x - mx) + __expf(v.y - mx)) + (__expf(v.z - mx) + __expf(v.w - mx));
    }
    red[tid] = sum;
    __syncthreads();
    for (int s = 128; s > 0; s >>= 1) { if (tid < s) red[tid] += red[tid + s]; __syncthreads(); }
    if (tid == 0) {
        d_mx[bm] = mx;
        d_wj[bm] = gam[0] / red[0];
    }
}

// ---------------- 12) o_part = sum_{j in half} hn[c,j]·exp(s[j,m]-mx_j)  (j-split 2) ----------------
__global__ void k_ogemm() {
    int b = blockIdx.y;
    int m0 = blockIdx.x * 64;
    int js = blockIdx.z;
    __shared__ float Bs[32][64];
    __shared__ float Hs[32][144];
    int tid = threadIdx.x;
    int mi = tid & 15, ci = tid >> 4;   // m = m0+mi*4.., c-pairs ci*8+2cp; ci==0 also c=128,129
    float2 acc[4][4] = {};   // [cpair][m]
    float2 ace[4] = {};      // ci==0: (o[128,m], o[129,m])
    const int jbeg = js * (M_ / JS), jend = jbeg + M_ / JS;
    for (int j0 = jbeg; j0 < jend; j0 += 32) {
        // stage exp'd s tile: 32 x 64 (2 float4 per thread)
        for (int e = tid; e < 32 * 16; e += 256) {
            int k = e >> 4, c4 = e & 15;
            float4 v = *(const float4*)&d_s[((size_t)(b * M_ + j0 + k)) * M_ + m0 + c4 * 4];
            float mxv = d_mx[b * M_ + j0 + k];
            float4 p;
            p.x = __expf(v.x - mxv); p.y = __expf(v.y - mxv);
            p.z = __expf(v.z - mxv); p.w = __expf(v.w - mxv);
            *(float4*)&Bs[k][c4 * 4] = p;
        }
        // stage h (gamma/Z already folded): 32 x 144
        for (int e = tid; e < 32 * 144; e += 256) {
            int c = e >> 5, k = e & 31;
            Hs[k][c] = (c < CH) ? d_hn[(b * CH + c) * M_ + j0 + k] : 0.f;
        }
        __syncthreads();
#pragma unroll
        for (int k = 0; k < 32; k++) {
            float4 bv = *(const float4*)&Bs[k][mi * 4];
            float2 pm0 = pack2(bv.x), pm1 = pack2(bv.y), pm2 = pack2(bv.z), pm3 = pack2(bv.w);
            float4 h0 = *(const float4*)&Hs[k][ci * 8];
            float4 h1 = *(const float4*)&Hs[k][ci * 8 + 4];
            float2 hp0 = make_float2(h0.x, h0.y), hp1 = make_float2(h0.z, h0.w);
            float2 hp2 = make_float2(h1.x, h1.y), hp3 = make_float2(h1.z, h1.w);
            acc[0][0] = ffma2(hp0, pm0, acc[0][0]); acc[0][1] = ffma2(hp0, pm1, acc[0][1]);
            acc[0][2] = ffma2(hp0, pm2, acc[0][2]); acc[0][3] = ffma2(hp0, pm3, acc[0][3]);
            acc[1][0] = ffma2(hp1, pm0, acc[1][0]); acc[1][1] = ffma2(hp1, pm1, acc[1][1]);
            acc[1][2] = ffma2(hp1, pm2, acc[1][2]); acc[1][3] = ffma2(hp1, pm3, acc[1][3]);
            acc[2][0] = ffma2(hp2, pm0, acc[2][0]); acc[2][1] = ffma2(hp2, pm1, acc[2][1]);
            acc[2][2] = ffma2(hp2, pm2, acc[2][2]); acc[2][3] = ffma2(hp2, pm3, acc[2][3]);
            acc[3][0] = ffma2(hp3, pm0, acc[3][0]); acc[3][1] = ffma2(hp3, pm1, acc[3][1]);
            acc[3][2] = ffma2(hp3, pm2, acc[3][2]); acc[3][3] = ffma2(hp3, pm3, acc[3][3]);
            if (ci == 0) {
                float2 he = *(const float2*)&Hs[k][128];
                ace[0] = ffma2(he, pm0, ace[0]); ace[1] = ffma2(he, pm1, ace[1]);
                ace[2] = ffma2(he, pm2, ace[2]); ace[3] = ffma2(he, pm3, ace[3]);
            }
        }
        __syncthreads();
    }
    float* outp = &d_op[(size_t)js * B_ * CH * M_];
#pragma unroll
    for (int cp = 0; cp < 4; cp++) {
        int c0 = ci * 8 + 2 * cp, c1 = c0 + 1;
        *(float4*)&outp[(b * CH + c0) * M_ + m0 + mi * 4] = make_float4(
            acc[cp][0].x, acc[cp][1].x, acc[cp][2].x, acc[cp][3].x);
        *(float4*)&outp[(b * CH + c1) * M_ + m0 + mi * 4] = make_float4(
            acc[cp][0].y, acc[cp][1].y, acc[cp][2].y, acc[cp][3].y);
    }
    if (ci == 0) {
        *(float4*)&outp[(b * CH + 128) * M_ + m0 + mi * 4] = make_float4(
            ace[0].x, ace[1].x, ace[2].x, ace[3].x);
        *(float4*)&outp[(b * CH + 129) * M_ + m0 + mi * 4] = make_float4(
            ace[0].y, ace[1].y, ace[2].y, ace[3].y);
    }
}

// ---------------- 13) combine partials + residual ----------------
__global__ void k_comb() {
    int t = blockIdx.x * 256 + threadIdx.x;
    const size_t T = (size_t)B_ * CH * M_;
    if (t >= (int)T) return;
    d_n4[t] = d_op[t] + d_op[T + t] + d_net3[t];
}

// ---------------- 14) y1 = relu(W1 @ net4 + b1)   (256x130), q-split ----------------
__global__ void k_mlp1(const float* __restrict__ W, const float* __restrict__ bias) {
    int b = blockIdx.y, m0 = blockIdx.x * 64, half = blockIdx.z;
    __shared__ float In[CH][64];
    int tid = threadIdx.x;
    for (int e = tid; e < CH * 64; e += 256) {
        int k = e >> 6, i = e & 63;
        In[k][i] = d_n4[(b * CH + k) * M_ + m0 + i];
    }
    __syncthreads();
    int mi = tid & 15, ri = tid >> 4;
    int rbase = half * 128 + ri;
    const float* wp[8];
#pragma unroll
    for (int q = 0; q < 8; q++) wp[q] = W + (rbase + 16 * q) * CH;
    float acc[8][4] = {};
#pragma unroll 2
    for (int k = 0; k < CH; k++) {
        float4 iv = *(const float4*)&In[k][mi * 4];
#pragma unroll
        for (int q = 0; q < 8; q++) {
            float w = wp[q][k];
            acc[q][0] = fmaf(w, iv.x, acc[q][0]);
            acc[q][1] = fmaf(w, iv.y, acc[q][1]);
            acc[q][2] = fmaf(w, iv.z, acc[q][2]);
            acc[q][3] = fmaf(w, iv.w, acc[q][3]);
        }
    }
#pragma unroll
    for (int q = 0; q < 8; q++) {
        int r = rbase + 16 * q;
        float bv = bias[r];
        *(float4*)&d_y1[((size_t)b * MID + r) * M_ + m0 + mi * 4] =
            make_float4(fmaxf(acc[q][0] + bv, 0.f), fmaxf(acc[q][1] + bv, 0.f),
                        fmaxf(acc[q][2] + bv, 0.f), fmaxf(acc[q][3] + bv, 0.f));
    }
}

// ---------------- 15) out = relu(W2 @ y1 + b2)   (128x256), q-split ----------------
__global__ void k_mlp2(const float* __restrict__ W, const float* __restrict__ bias,
                       float* __restrict__ Out) {
    int b = blockIdx.y, m0 = blockIdx.x * 32;
    __shared__ float In[MID][32];
    int tid = threadIdx.x;
    for (int e = tid; e < MID * 32; e += 256) {
        int k = e >> 5, i = e & 31;
        In[k][i] = d_y1[((size_t)b * MID + k) * M_ + m0 + i];
    }
    __syncthreads();
    int mi = tid & 7, ri = tid >> 3;     // 8 m-groups (32 m), 32 r-groups
    const float* wp[4];
#pragma unroll
    for (int q = 0; q < 4; q++) wp[q] = W + (ri + 32 * q) * MID;
    float acc[4][4] = {};
#pragma unroll 4
    for (int k = 0; k < MID; k++) {
        float4 iv = *(const float4*)&In[k][mi * 4];
#pragma unroll
        for (int q = 0; q < 4; q++) {
            float w = wp[q][k];
            acc[q][0] = fmaf(w, iv.x, acc[q][0]);
            acc[q][1] = fmaf(w, iv.y, acc[q][1]);
            acc[q][2] = fmaf(w, iv.z, acc[q][2]);
            acc[q][3] = fmaf(w, iv.w, acc[q][3]);
        }
    }
#pragma unroll
    for (int q = 0; q < 4; q++) {
        int r = ri + 32 * q;
        float bv = bias[r];
        *(float4*)&Out[((size_t)b * RO + r) * M_ + m0 + mi * 4] =
            make_float4(fmaxf(acc[q][0] + bv, 0.f), fmaxf(acc[q][1] + bv, 0.f),
                        fmaxf(acc[q][2] + bv, 0.f), fmaxf(acc[q][3] + bv, 0.f));
    }
}

// ---------------- launch ----------------
extern "C" void kernel_launch(void* const* d_in, const int* in_sizes, int n_in,
                              void* d_out, int out_size) {
    const float* x    = (const float*)d_in[0];
    const float* Wec  = (const float*)d_in[1];
    const float* g_ec = (const float*)d_in[2];
    const float* b_ec = (const float*)d_in[3];
    const float* Wf   = (const float*)d_in[4];
    const float* bf   = (const float*)d_in[5];
    const float* gf   = (const float*)d_in[6];
    const float* betf = (const float*)d_in[7];
    const float* Wg   = (const float*)d_in[8];
    const float* bg   = (const float*)d_in[9];
    const float* gg   = (const float*)d_in[10];
    const float* betg = (const float*)d_in[11];
    const float* Wh   = (const float*)d_in[12];
    const float* bh   = (const float*)d_in[13];
    const float* gh   = (const float*)d_in[14];
    const float* beth = (const float*)d_in[15];
    const float* gam  = (const float*)d_in[16];
    const float* W1   = (const float*)d_in[17];
    const float* b1   = (const float*)d_in[18];
    const float* W2   = (const float*)d_in[19];
    const float* b2   = (const float*)d_in[20];
    float* out = (float*)d_out;

    k_sq    <<<16, 256>>>(x);
    k_negd  <<<dim3(16, 16, 4), 256>>>(x);
    k_topk  <<<512, 256>>>();
    k_yb    <<<dim3(8, 16, 4), 256>>>(x, Wec);
    k_stats1<<<dim3(64, 4), 512>>>();
    k_red1  <<<2, 256>>>(g_ec, b_ec);
    k_edgemax<<<B_ * N_, 256>>>();
    k_grid  <<<64, 256>>>();
    k_fgh   <<<dim3(64, 4, 2), 256>>>(Wf, bf, Wg, bg, Wh, bh);
    k_stats2<<<194, 256>>>();
    k_norm2 <<<(B_ * CF * M_ + 255) / 256, 256>>>(0, gf, betf);
    k_norm2 <<<(B_ * CF * M_ + 255) / 256, 256>>>(1, gg, betg);
    k_sgemm <<<dim3(32, 64, 4), 256>>>();
    k_rowstats<<<B_ * M_, 256>>>(gam);
    k_norm2h<<<(B_ * CH * M_ + 255) / 256, 256>>>(gh, beth);
    k_ogemm <<<dim3(64, 4, JS), 256>>>();
    k_comb  <<<(B_ * CH * M_ + 255) / 256, 256>>>();
    k_mlp1  <<<dim3(64, 4, 2), 256>>>(W1, b1);
    k_mlp2  <<<dim3(128, 4), 256>>>(W2, b2, out);
}

// round 14
// speedup vs baseline: 1.0166x; 1.0166x over previous
#include <cuda_runtime.h>
#include <string.h>

// Problem constants
namespace {
constexpr int B_  = 4;
constexpr int C_  = 128;
constexpr int N_  = 1024;
constexpr int KNN = 20;
constexpr int M_  = 4096;   // N*UP
constexpr int OC  = 512;    // edge-conv out channels
constexpr int CH  = 130;    // net channels after grid concat
constexpr int CF  = 32;     // f/g channels
constexpr int MID = 256;    // W1 out
constexpr int RO  = 128;    // W2 out
}
#define EPS_ 1e-5f
#define NEGINF_ -3.4e38f
#define POSINF_ 3.4e38f

// ---- packed f32x2 FMA with defined-behavior punning ----
__device__ __forceinline__ float2 ffma2(float2 a, float2 b, float2 c) {
    unsigned long long au, bu, cu, du;
    memcpy(&au, &a, 8);
    memcpy(&bu, &b, 8);
    memcpy(&cu, &c, 8);
    asm("fma.rn.f32x2 %0, %1, %2, %3;" : "=l"(du) : "l"(au), "l"(bu), "l"(cu));
    float2 d;
    memcpy(&d, &du, 8);
    return d;
}
__device__ __forceinline__ float2 pack2(float x) { return make_float2(x, x); }

// ---- scratch (device globals; no allocations allowed) ----
__device__ float d_sq   [B_*N_];
__device__ float d_negd [B_*N_*N_];
__device__ int   d_idx  [B_*N_*KNN];
__device__ float d_Yt   [B_*N_*OC];    // [b][n][o]
__device__ float d_baset[B_*N_*OC];    // [b][n][o]
__device__ float d_st1p [2*256*OC];    // per-block partial sums (deterministic)
__device__ float d_st1  [2*OC];        // finalized: sc[o], sh[o]
__device__ float d_vmx  [B_*N_*OC];    // per-(n,o) max over k of raw edge value
__device__ float d_vmn  [B_*N_*OC];    // per-(n,o) min over k of raw edge value
__device__ float d_net3 [B_*CH*M_];    // [b][c][m]
__device__ float d_fr   [B_*CF*M_];
__device__ float d_gr   [B_*CF*M_];
__device__ float d_hr   [B_*CH*M_];
__device__ float d_st2  [2*(CF+CF+CH)];
__device__ float d_fn   [B_*CF*M_];
__device__ float d_gn   [B_*CF*M_];
__device__ float d_hn   [B_*CH*M_];
__device__ float d_s    [(size_t)B_*M_*M_];   // raw attention scores (never normalized)
__device__ float d_mx   [B_*M_];              // per-row max
__device__ float d_wj   [B_*M_];              // gamma / Z per row
__device__ float d_n4   [B_*CH*M_];
__device__ float d_y1   [B_*MID*M_];

// ---------------- 1) per-point squared norms ----------------
__global__ void k_sq(const float* __restrict__ x) {
    int t = blockIdx.x * 256 + threadIdx.x;      // B*N = 4096
    int b = t >> 10, n = t & 1023;
    const float* xb = x + b * C_ * N_ + n;
    float s = 0.f;
#pragma unroll 8
    for (int c = 0; c < C_; c++) { float v = xb[c * N_]; s = fmaf(v, v, s); }
    d_sq[t] = s;
}

// ---------------- 2) neg squared distance: 2 x^T x - sq_n - sq_m ----------------
__global__ void k_negd(const float* __restrict__ x) {
    int b = blockIdx.z;
    int n0 = blockIdx.y * 64, m0 = blockIdx.x * 64;
    __shared__ float As[32][64];
    __shared__ float Bs[32][64];
    int tid = threadIdx.x;
    const float* xb = x + b * C_ * N_;
    float2 acc[4][2] = {};
    for (int k0 = 0; k0 < C_; k0 += 32) {
        for (int e = tid; e < 32 * 64; e += 256) {
            int k = e >> 6, i = e & 63;
            As[k][i] = xb[(k0 + k) * N_ + n0 + i];
            Bs[k][i] = xb[(k0 + k) * N_ + m0 + i];
        }
        __syncthreads();
        int ty = tid >> 4, tx = tid & 15;
#pragma unroll
        for (int k = 0; k < 32; k++) {
            float2 b0 = *(const float2*)&Bs[k][tx * 4];
            float2 b1 = *(const float2*)&Bs[k][tx * 4 + 2];
#pragma unroll
            for (int i = 0; i < 4; i++) {
                float2 av = pack2(As[k][ty * 4 + i]);
                acc[i][0] = ffma2(av, b0, acc[i][0]);
                acc[i][1] = ffma2(av, b1, acc[i][1]);
            }
        }
        __syncthreads();
    }
    int ty = tid >> 4, tx = tid & 15;
#pragma unroll
    for (int i = 0; i < 4; i++) {
        int n = n0 + ty * 4 + i;
        float sn = d_sq[b * N_ + n];
        float4 o;
        o.x = 2.f * acc[i][0].x - sn - d_sq[b * N_ + m0 + tx * 4 + 0];
        o.y = 2.f * acc[i][0].y - sn - d_sq[b * N_ + m0 + tx * 4 + 1];
        o.z = 2.f * acc[i][1].x - sn - d_sq[b * N_ + m0 + tx * 4 + 2];
        o.w = 2.f * acc[i][1].y - sn - d_sq[b * N_ + m0 + tx * 4 + 3];
        *(float4*)&d_negd[(b * N_ + n) * N_ + m0 + tx * 4] = o;
    }
}

// ---------------- 3) top-k (k=20), warp per row, tie -> lower index ----------------
__global__ void k_topk() {
    int row = blockIdx.x * 8 + (threadIdx.x >> 5);    // 4096 rows
    int lane = threadIdx.x & 31;
    const float* src = &d_negd[(size_t)row * N_];
    float v[32];
#pragma unroll
    for (int i = 0; i < 32; i++) v[i] = src[lane + i * 32];
    for (int t = 0; t < KNN; t++) {
        float bv = v[0]; int bi = lane;
#pragma unroll
        for (int i = 1; i < 32; i++) {
            int gi = i * 32 + lane;
            float vv = v[i];
            if (vv > bv || (vv == bv && gi < bi)) { bv = vv; bi = gi; }
        }
#pragma unroll
        for (int off = 16; off > 0; off >>= 1) {
            float ov = __shfl_down_sync(0xffffffff, bv, off);
            int   oi = __shfl_down_sync(0xffffffff, bi, off);
            if (ov > bv || (ov == bv && oi < bi)) { bv = ov; bi = oi; }
        }
        bi = __shfl_sync(0xffffffff, bi, 0);
        if (lane == 0) d_idx[row * KNN + t] = bi;
        int slot = bi >> 5;
        bool mine = (bi & 31) == lane;
#pragma unroll
        for (int i = 0; i < 32; i++) if (i == slot && mine) v[i] = NEGINF_;
    }
}

// ---------------- 4) Y = Wa@x, base = (Wb-Wa)@x, both point-major (coalesced Wec) ----------------
__global__ void k_yb(const float* __restrict__ x, const float* __restrict__ Wec) {
    int b = blockIdx.z;
    int n0 = blockIdx.y * 64;   // 16
    int o0 = blockIdx.x * 64;   // 8
    __shared__ float Xs[32][66];
    __shared__ float Was[32][66];
    __shared__ float Wbs[32][66];
    int tid = threadIdx.x;
    float2 a1[4][2] = {}, a2[4][2] = {};
    for (int k0 = 0; k0 < C_; k0 += 32) {
        for (int e = tid; e < 32 * 64; e += 256) {
            int k = e >> 6, i = e & 63;
            Xs[k][i] = x[b * C_ * N_ + (k0 + k) * N_ + n0 + i];
        }
        for (int e = tid; e < 64 * 32; e += 256) {
            int i = e >> 5, k = e & 31;
            float wa = Wec[(o0 + i) * 256 + k0 + k];
            float wb = Wec[(o0 + i) * 256 + 128 + k0 + k];
            Was[k][i] = wa;
            Wbs[k][i] = wb - wa;
        }
        __syncthreads();
        int ty = tid >> 4, tx = tid & 15;   // ty -> n, tx -> o
#pragma unroll
        for (int k = 0; k < 32; k++) {
            float2 wa0 = *(const float2*)&Was[k][tx * 4];
            float2 wa1 = *(const float2*)&Was[k][tx * 4 + 2];
            float2 wb0 = *(const float2*)&Wbs[k][tx * 4];
            float2 wb1 = *(const float2*)&Wbs[k][tx * 4 + 2];
#pragma unroll
            for (int i = 0; i < 4; i++) {
                float2 xv = pack2(Xs[k][ty * 4 + i]);
                a1[i][0] = ffma2(xv, wa0, a1[i][0]);
                a1[i][1] = ffma2(xv, wa1, a1[i][1]);
                a2[i][0] = ffma2(xv, wb0, a2[i][0]);
                a2[i][1] = ffma2(xv, wb1, a2[i][1]);
            }
        }
        __syncthreads();
    }
    int ty = tid >> 4, tx = tid & 15;
#pragma unroll
    for (int i = 0; i < 4; i++) {
        int n = n0 + ty * 4 + i;
        *(float4*)&d_Yt   [(b * N_ + n) * OC + o0 + tx * 4] =
            make_float4(a1[i][0].x, a1[i][0].y, a1[i][1].x, a1[i][1].y);
        *(float4*)&d_baset[(b * N_ + n) * OC + o0 + tx * 4] =
            make_float4(a2[i][0].x, a2[i][0].y, a2[i][1].x, a2[i][1].y);
    }
}

// ---------------- 5) BN stats + per-(n,o) max/min over k (single gather pass) ----------------
__global__ void k_stats1() {
    int b = blockIdx.y;
    int nc = blockIdx.x;            // 64 chunks of 16 points
    int p = b * 64 + nc;
    int o = threadIdx.x;            // 512
    __shared__ int sidx[16 * KNN];
    for (int e = threadIdx.x; e < 16 * KNN; e += 512)
        sidx[e] = d_idx[(b * N_ + nc * 16) * KNN + e];
    __syncthreads();
    float s = 0.f, ss = 0.f;
    for (int nn = 0; nn < 16; nn++) {
        int n = nc * 16 + nn;
        float bv = d_baset[(b * N_ + n) * OC + o];
        float vmx = NEGINF_, vmn = POSINF_;
#pragma unroll
        for (int k = 0; k < KNN; k++) {
            int j = sidx[nn * KNN + k];
            float v = d_Yt[(b * N_ + j) * OC + o] + bv;
            s += v; ss = fmaf(v, v, ss);
            vmx = fmaxf(vmx, v);
            vmn = fminf(vmn, v);
        }
        d_vmx[(b * N_ + n) * OC + o] = vmx;
        d_vmn[(b * N_ + n) * OC + o] = vmn;
    }
    d_st1p[p * OC + o] = s;
    d_st1p[(256 + p) * OC + o] = ss;
}

// reduce partials AND finalize BN scale/shift: d_st1[o]=sc, d_st1[OC+o]=sh
__global__ void k_red1(const float* __restrict__ g_ec, const float* __restrict__ b_ec) {
    int o = blockIdx.x * 256 + threadIdx.x;
    if (o >= OC) return;
    float s = 0.f, ss = 0.f;
    for (int p = 0; p < 256; p++) { s += d_st1p[p * OC + o]; ss += d_st1p[(256 + p) * OC + o]; }
    const float cnt = (float)(B_ * N_ * KNN);
    float mean = s / cnt;
    float var  = ss / cnt - mean * mean;
    float sc = rsqrtf(var + EPS_) * g_ec[o];
    d_st1[o] = sc;
    d_st1[OC + o] = b_ec[o] - mean * sc;
}

// ---------------- 6) edgemax, now elementwise (max commutes through monotone affine+leaky) ----------------
__global__ void k_edgemax() {
    int t = blockIdx.x * 256 + threadIdx.x;   // B*N*OC = 2M
    if (t >= B_ * N_ * OC) return;
    int o = t & (OC - 1);
    int bn = t >> 9;
    int b = bn >> 10, n = bn & 1023;
    float sc = d_st1[o];
    float sh = d_st1[OC + o];
    float v = (sc >= 0.f) ? d_vmx[t] : d_vmn[t];
    v = fmaf(v, sc, sh);
    v = v > 0.f ? v : 0.2f * v;
    int u = o >> 7, c = o & 127;
    d_net3[(b * CH + c) * M_ + n * 4 + u] = v;
}

__global__ void k_grid() {
    int t = blockIdx.x * 256 + threadIdx.x;   // B*M = 16384
    int b = t >> 12, m = t & 4095;
    int gi = m >> 10;
    float gx = (gi < 2) ? -0.2f : 0.2f;
    float gy = (gi & 1) ? 0.2f : -0.2f;
    d_net3[(b * CH + 128) * M_ + m] = gx;
    d_net3[(b * CH + 129) * M_ + m] = gy;
}

// ---------------- 7) f/g/h raw convs (K=130), q-split row assignment ----------------
__global__ void k_fgh(const float* __restrict__ Wf, const float* __restrict__ bf,
                      const float* __restrict__ Wg, const float* __restrict__ bg,
                      const float* __restrict__ Wh, const float* __restrict__ bh) {
    int b = blockIdx.y, m0 = blockIdx.x * 64, half = blockIdx.z;
    __shared__ float In[CH][64];
    int tid = threadIdx.x;
    for (int e = tid; e < CH * 64; e += 256) {
        int k = e >> 6, i = e & 63;
        In[k][i] = d_net3[(b * CH + k) * M_ + m0 + i];
    }
    __syncthreads();
    int mi = tid & 15, ri = tid >> 4;
    int rbase = half * 112 + ri;
    const float* wp[7]; float bs_[7]; float* op[7]; bool val[7];
#pragma unroll
    for (int q = 0; q < 7; q++) {
        int r = rbase + 16 * q;
        val[q] = (r < 194);
        if (!val[q]) { wp[q] = Wf; bs_[q] = 0.f; op[q] = d_fr; continue; }
        if (r < 32)      { wp[q] = Wf + r * CH;          bs_[q] = bf[r];      op[q] = &d_fr[(b * CF + r) * M_]; }
        else if (r < 64) { int c = r - 32; wp[q] = Wg + c * CH; bs_[q] = bg[c]; op[q] = &d_gr[(b * CF + c) * M_]; }
        else             { int c = r - 64; wp[q] = Wh + c * CH; bs_[q] = bh[c]; op[q] = &d_hr[(b * CH + c) * M_]; }
    }
    float acc[7][4] = {};
#pragma unroll 2
    for (int k = 0; k < CH; k++) {
        float4 iv = *(const float4*)&In[k][mi * 4];
#pragma unroll
        for (int q = 0; q < 7; q++) {
            float w = wp[q][k];
            acc[q][0] = fmaf(w, iv.x, acc[q][0]);
            acc[q][1] = fmaf(w, iv.y, acc[q][1]);
            acc[q][2] = fmaf(w, iv.z, acc[q][2]);
            acc[q][3] = fmaf(w, iv.w, acc[q][3]);
        }
    }
#pragma unroll
    for (int q = 0; q < 7; q++) {
        if (val[q]) {
            float bv = bs_[q];
            *(float4*)&op[q][m0 + mi * 4] =
                make_float4(acc[q][0] + bv, acc[q][1] + bv, acc[q][2] + bv, acc[q][3] + bv);
        }
    }
}

// ---------------- 8) BN stats for f/g/h (one block per channel) ----------------
__global__ void k_stats2() {
    int ch = blockIdx.x, tid = threadIdx.x;   // 194 channels
    __shared__ float r1[256], r2[256];
    float s = 0.f, ss = 0.f;
    for (int b = 0; b < B_; b++) {
        const float* p;
        if (ch < 32)      p = &d_fr[(b * CF + ch) * M_];
        else if (ch < 64) p = &d_gr[(b * CF + (ch - 32)) * M_];
        else              p = &d_hr[(b * CH + (ch - 64)) * M_];
        for (int m = tid; m < M_; m += 256) { float v = p[m]; s += v; ss = fmaf(v, v, ss); }
    }
    r1[tid] = s; r2[tid] = ss;
    __syncthreads();
    for (int st = 128; st > 0; st >>= 1) {
        if (tid < st) { r1[tid] += r1[tid + st]; r2[tid] += r2[tid + st]; }
        __syncthreads();
    }
    if (tid == 0) { d_st2[ch] = r1[0]; d_st2[194 + ch] = r2[0]; }
}

// ---------------- 9) normalize + relu (sel: 0=f, 1=g, 2=h) ----------------
__global__ void k_norm2(int sel, const float* __restrict__ gamma, const float* __restrict__ beta) {
    int t = blockIdx.x * 256 + threadIdx.x;
    int Cdim = (sel == 2) ? CH : CF;
    int total = B_ * Cdim * M_;
    if (t >= total) return;
    int c = (t / M_) % Cdim;
    int off = (sel == 0) ? 0 : (sel == 1) ? 32 : 64;
    const float cntf = (float)(B_ * M_);
    float mean = d_st2[off + c] / cntf;
    float var  = d_st2[194 + off + c] / cntf - mean * mean;
    float sc = rsqrtf(var + EPS_) * gamma[c];
    float sh = beta[c] - mean * sc;
    const float* raw = (sel == 0) ? d_fr : (sel == 1) ? d_gr : d_hr;
    float* outp      = (sel == 0) ? d_fn : (sel == 1) ? d_gn : d_hn;
    outp[t] = fmaxf(fmaf(raw[t], sc, sh), 0.f);
}

// ---------------- 10) s[b,m,n] = sum_c g[c,m] f[c,n]  (K=32, 64m x 128n tiles) ----------------
__global__ void k_sgemm() {
    int b = blockIdx.z;
    int m0 = blockIdx.y * 64, n0 = blockIdx.x * 128;
    __shared__ float Gs[CF][64];
    __shared__ float Fs[CF][128];
    int tid = threadIdx.x;
    for (int e = tid; e < CF * 64; e += 256) {
        int k = e >> 6, i = e & 63;
        Gs[k][i] = d_gn[(b * CF + k) * M_ + m0 + i];
    }
    for (int e = tid; e < CF * 128; e += 256) {
        int k = e >> 7, i = e & 127;
        Fs[k][i] = d_fn[(b * CF + k) * M_ + n0 + i];
    }
    __syncthreads();
    int ty = tid >> 4, tx = tid & 15;   // ty -> m group (4), tx -> n group (8)
    float2 acc[4][4] = {};
#pragma unroll
    for (int k = 0; k < CF; k++) {
        float4 gv = *(const float4*)&Gs[k][ty * 4];
        float4 fa = *(const float4*)&Fs[k][tx * 8];
        float4 fb = *(const float4*)&Fs[k][tx * 8 + 4];
        float gm[4] = {gv.x, gv.y, gv.z, gv.w};
        float2 fn0 = make_float2(fa.x, fa.y), fn1 = make_float2(fa.z, fa.w);
        float2 fn2 = make_float2(fb.x, fb.y), fn3 = make_float2(fb.z, fb.w);
#pragma unroll
        for (int i = 0; i < 4; i++) {
            float2 gp = pack2(gm[i]);
            acc[i][0] = ffma2(gp, fn0, acc[i][0]);
            acc[i][1] = ffma2(gp, fn1, acc[i][1]);
            acc[i][2] = ffma2(gp, fn2, acc[i][2]);
            acc[i][3] = ffma2(gp, fn3, acc[i][3]);
        }
    }
#pragma unroll
    for (int i = 0; i < 4; i++) {
        int m = m0 + ty * 4 + i;
        float* dst = &d_s[((size_t)(b * M_ + m)) * M_ + n0 + tx * 8];
        *(float4*)&dst[0] = make_float4(acc[i][0].x, acc[i][0].y, acc[i][1].x, acc[i][1].y);
        *(float4*)&dst[4] = make_float4(acc[i][2].x, acc[i][2].y, acc[i][3].x, acc[i][3].y);
    }
}

// ---------------- 11) row stats: mx, wj = gamma/Z (no writeback to d_s) ----------------
__global__ void k_rowstats(const float* __restrict__ gam) {
    int bm = blockIdx.x;     // B*M rows
    __shared__ float row[M_];
    __shared__ float red[256];
    const float* src = &d_s[(size_t)bm * M_];
    int tid = threadIdx.x;
    float mx = NEGINF_;
    for (int i = tid * 4; i < M_; i += 1024) {
        float4 v = *(const float4*)&src[i];
        *(float4*)&row[i] = v;
        mx = fmaxf(mx, fmaxf(fmaxf(v.x, v.y), fmaxf(v.z, v.w)));
    }
    red[tid] = mx;
    __syncthreads();
    for (int s = 128; s > 0; s >>= 1) { if (tid < s) red[tid] = fmaxf(red[tid], red[tid + s]); __syncthreads(); }
    mx = red[0];
    __syncthreads();
    float sum = 0.f;
    for (int i = tid * 4; i < M_; i += 1024) {
        float4 v = *(const float4*)&row[i];
        sum += (__expf(v.x - mx) + __expf(v.y - mx)) + (__expf(v.z - mx) + __expf(v.w - mx));
    }
    red[tid] = sum;
    __syncthreads();
    for (int s = 128; s > 0; s >>= 1) { if (tid < s) red[tid] += red[tid + s]; __syncthreads(); }
    if (tid == 0) {
        d_mx[bm] = mx;
        d_wj[bm] = gam[0] / red[0];
    }
}

// ---------------- 11b) fold wj into h: d_hn[b][c][j] *= wj[b][j] ----------------
__global__ void k_hmul() {
    int t = blockIdx.x * 256 + threadIdx.x;
    if (t >= B_ * CH * M_) return;
    int m = t % M_;
    int b = t / (CH * M_);
    d_hn[t] *= d_wj[b * M_ + m];
}

// ---------------- 12) n4 = sum_j hn[c,j]·exp(s[j,m]-mx_j) + net3  (k-tile 32) ----------------
__global__ void k_ogemm() {
    int b = blockIdx.y;
    int m0 = blockIdx.x * 64;
    __shared__ float Bs[32][64];
    __shared__ float Hs[32][144];
    int tid = threadIdx.x;
    int mi = tid & 15, ci = tid >> 4;   // m = m0+mi*4.., c-pairs ci*8+2cp; ci==0 also c=128,129
    float2 acc[4][4] = {};   // [cpair][m]
    float2 ace[4] = {};      // ci==0: (o[128,m], o[129,m])
    for (int j0 = 0; j0 < M_; j0 += 32) {
        // stage exp'd s tile: 32 x 64 (2 float4 per thread)
        for (int e = tid; e < 32 * 16; e += 256) {
            int k = e >> 4, c4 = e & 15;
            float4 v = *(const float4*)&d_s[((size_t)(b * M_ + j0 + k)) * M_ + m0 + c4 * 4];
            float mxv = d_mx[b * M_ + j0 + k];
            float4 p;
            p.x = __expf(v.x - mxv); p.y = __expf(v.y - mxv);
            p.z = __expf(v.z - mxv); p.w = __expf(v.w - mxv);
            *(float4*)&Bs[k][c4 * 4] = p;
        }
        // stage h (gamma/Z already folded): 32 x 144
        for (int e = tid; e < 32 * 144; e += 256) {
            int c = e >> 5, k = e & 31;
            Hs[k][c] = (c < CH) ? d_hn[(b * CH + c) * M_ + j0 + k] : 0.f;
        }
        __syncthreads();
#pragma unroll
        for (int k = 0; k < 32; k++) {
            float4 bv = *(const float4*)&Bs[k][mi * 4];
            float2 pm0 = pack2(bv.x), pm1 = pack2(bv.y), pm2 = pack2(bv.z), pm3 = pack2(bv.w);
            float4 h0 = *(const float4*)&Hs[k][ci * 8];
            float4 h1 = *(const float4*)&Hs[k][ci * 8 + 4];
            float2 hp0 = make_float2(h0.x, h0.y), hp1 = make_float2(h0.z, h0.w);
            float2 hp2 = make_float2(h1.x, h1.y), hp3 = make_float2(h1.z, h1.w);
            acc[0][0] = ffma2(hp0, pm0, acc[0][0]); acc[0][1] = ffma2(hp0, pm1, acc[0][1]);
            acc[0][2] = ffma2(hp0, pm2, acc[0][2]); acc[0][3] = ffma2(hp0, pm3, acc[0][3]);
            acc[1][0] = ffma2(hp1, pm0, acc[1][0]); acc[1][1] = ffma2(hp1, pm1, acc[1][1]);
            acc[1][2] = ffma2(hp1, pm2, acc[1][2]); acc[1][3] = ffma2(hp1, pm3, acc[1][3]);
            acc[2][0] = ffma2(hp2, pm0, acc[2][0]); acc[2][1] = ffma2(hp2, pm1, acc[2][1]);
            acc[2][2] = ffma2(hp2, pm2, acc[2][2]); acc[2][3] = ffma2(hp2, pm3, acc[2][3]);
            acc[3][0] = ffma2(hp3, pm0, acc[3][0]); acc[3][1] = ffma2(hp3, pm1, acc[3][1]);
            acc[3][2] = ffma2(hp3, pm2, acc[3][2]); acc[3][3] = ffma2(hp3, pm3, acc[3][3]);
            if (ci == 0) {
                float2 he = *(const float2*)&Hs[k][128];
                ace[0] = ffma2(he, pm0, ace[0]); ace[1] = ffma2(he, pm1, ace[1]);
                ace[2] = ffma2(he, pm2, ace[2]); ace[3] = ffma2(he, pm3, ace[3]);
            }
        }
        __syncthreads();
    }
#pragma unroll
    for (int cp = 0; cp < 4; cp++) {
        int c0 = ci * 8 + 2 * cp, c1 = c0 + 1;
        float4 va = *(const float4*)&d_net3[(b * CH + c0) * M_ + m0 + mi * 4];
        float4 vb = *(const float4*)&d_net3[(b * CH + c1) * M_ + m0 + mi * 4];
        *(float4*)&d_n4[(b * CH + c0) * M_ + m0 + mi * 4] = make_float4(
            acc[cp][0].x + va.x, acc[cp][1].x + va.y, acc[cp][2].x + va.z, acc[cp][3].x + va.w);
        *(float4*)&d_n4[(b * CH + c1) * M_ + m0 + mi * 4] = make_float4(
            acc[cp][0].y + vb.x, acc[cp][1].y + vb.y, acc[cp][2].y + vb.z, acc[cp][3].y + vb.w);
    }
    if (ci == 0) {
        float4 va = *(const float4*)&d_net3[(b * CH + 128) * M_ + m0 + mi * 4];
        float4 vb = *(const float4*)&d_net3[(b * CH + 129) * M_ + m0 + mi * 4];
        *(float4*)&d_n4[(b * CH + 128) * M_ + m0 + mi * 4] = make_float4(
            ace[0].x + va.x, ace[1].x + va.y, ace[2].x + va.z, ace[3].x + va.w);
        *(float4*)&d_n4[(b * CH + 129) * M_ + m0 + mi * 4] = make_float4(
            ace[0].y + vb.x, ace[1].y + vb.y, ace[2].y + vb.z, ace[3].y + vb.w);
    }
}

// ---------------- 14) y1 = relu(W1 @ net4 + b1)   (256x130), q-split ----------------
__global__ void k_mlp1(const float* __restrict__ W, const float* __restrict__ bias) {
    int b = blockIdx.y, m0 = blockIdx.x * 64, half = blockIdx.z;
    __shared__ float In[CH][64];
    int tid = threadIdx.x;
    for (int e = tid; e < CH * 64; e += 256) {
        int k = e >> 6, i = e & 63;
        In[k][i] = d_n4[(b * CH + k) * M_ + m0 + i];
    }
    __syncthreads();
    int mi = tid & 15, ri = tid >> 4;
    int rbase = half * 128 + ri;
    const float* wp[8];
#pragma unroll
    for (int q = 0; q < 8; q++) wp[q] = W + (rbase + 16 * q) * CH;
    float acc[8][4] = {};
#pragma unroll 2
    for (int k = 0; k < CH; k++) {
        float4 iv = *(const float4*)&In[k][mi * 4];
#pragma unroll
        for (int q = 0; q < 8; q++) {
            float w = wp[q][k];
            acc[q][0] = fmaf(w, iv.x, acc[q][0]);
            acc[q][1] = fmaf(w, iv.y, acc[q][1]);
            acc[q][2] = fmaf(w, iv.z, acc[q][2]);
            acc[q][3] = fmaf(w, iv.w, acc[q][3]);
        }
    }
#pragma unroll
    for (int q = 0; q < 8; q++) {
        int r = rbase + 16 * q;
        float bv = bias[r];
        *(float4*)&d_y1[((size_t)b * MID + r) * M_ + m0 + mi * 4] =
            make_float4(fmaxf(acc[q][0] + bv, 0.f), fmaxf(acc[q][1] + bv, 0.f),
                        fmaxf(acc[q][2] + bv, 0.f), fmaxf(acc[q][3] + bv, 0.f));
    }
}

// ---------------- 15) out = relu(W2 @ y1 + b2)   (128x256), q-split ----------------
__global__ void k_mlp2(const float* __restrict__ W, const float* __restrict__ bias,
                       float* __restrict__ Out) {
    int b = blockIdx.y, m0 = blockIdx.x * 32;
    __shared__ float In[MID][32];
    int tid = threadIdx.x;
    for (int e = tid; e < MID * 32; e += 256) {
        int k = e >> 5, i = e & 31;
        In[k][i] = d_y1[((size_t)b * MID + k) * M_ + m0 + i];
    }
    __syncthreads();
    int mi = tid & 7, ri = tid >> 3;     // 8 m-groups (32 m), 32 r-groups
    const float* wp[4];
#pragma unroll
    for (int q = 0; q < 4; q++) wp[q] = W + (ri + 32 * q) * MID;
    float acc[4][4] = {};
#pragma unroll 4
    for (int k = 0; k < MID; k++) {
        float4 iv = *(const float4*)&In[k][mi * 4];
#pragma unroll
        for (int q = 0; q < 4; q++) {
            float w = wp[q][k];
            acc[q][0] = fmaf(w, iv.x, acc[q][0]);
            acc[q][1] = fmaf(w, iv.y, acc[q][1]);
            acc[q][2] = fmaf(w, iv.z, acc[q][2]);
            acc[q][3] = fmaf(w, iv.w, acc[q][3]);
        }
    }
#pragma unroll
    for (int q = 0; q < 4; q++) {
        int r = ri + 32 * q;
        float bv = bias[r];
        *(float4*)&Out[((size_t)b * RO + r) * M_ + m0 + mi * 4] =
            make_float4(fmaxf(acc[q][0] + bv, 0.f), fmaxf(acc[q][1] + bv, 0.f),
                        fmaxf(acc[q][2] + bv, 0.f), fmaxf(acc[q][3] + bv, 0.f));
    }
}

// ---------------- launch ----------------
extern "C" void kernel_launch(void* const* d_in, const int* in_sizes, int n_in,
                              void* d_out, int out_size) {
    const float* x    = (const float*)d_in[0];
    const float* Wec  = (const float*)d_in[1];
    const float* g_ec = (const float*)d_in[2];
    const float* b_ec = (const float*)d_in[3];
    const float* Wf   = (const float*)d_in[4];
    const float* bf   = (const float*)d_in[5];
    const float* gf   = (const float*)d_in[6];
    const float* betf = (const float*)d_in[7];
    const float* Wg   = (const float*)d_in[8];
    const float* bg   = (const float*)d_in[9];
    const float* gg   = (const float*)d_in[10];
    const float* betg = (const float*)d_in[11];
    const float* Wh   = (const float*)d_in[12];
    const float* bh   = (const float*)d_in[13];
    const float* gh   = (const float*)d_in[14];
    const float* beth = (const float*)d_in[15];
    const float* gam  = (const float*)d_in[16];
    const float* W1   = (const float*)d_in[17];
    const float* b1   = (const float*)d_in[18];
    const float* W2   = (const float*)d_in[19];
    const float* b2   = (const float*)d_in[20];
    float* out = (float*)d_out;

    k_sq    <<<16, 256>>>(x);
    k_negd  <<<dim3(16, 16, 4), 256>>>(x);
    k_topk  <<<512, 256>>>();
    k_yb    <<<dim3(8, 16, 4), 256>>>(x, Wec);
    k_stats1<<<dim3(64, 4), 512>>>();
    k_red1  <<<2, 256>>>(g_ec, b_ec);
    k_edgemax<<<(B_ * N_ * OC + 255) / 256, 256>>>();
    k_grid  <<<64, 256>>>();
    k_fgh   <<<dim3(64, 4, 2), 256>>>(Wf, bf, Wg, bg, Wh, bh);
    k_stats2<<<194, 256>>>();
    k_norm2 <<<(B_ * CF * M_ + 255) / 256, 256>>>(0, gf, betf);
    k_norm2 <<<(B_ * CF * M_ + 255) / 256, 256>>>(1, gg, betg);
    k_norm2 <<<(B_ * CH * M_ + 255) / 256, 256>>>(2, gh, beth);
    k_sgemm <<<dim3(32, 64, 4), 256>>>();
    k_rowstats<<<B_ * M_, 256>>>(gam);
    k_hmul  <<<(B_ * CH * M_ + 255) / 256, 256>>>();
    k_ogemm <<<dim3(64, 4), 256>>>();
    k_mlp1  <<<dim3(64, 4, 2), 256>>>(W1, b1);
    k_mlp2  <<<dim3(128, 4), 256>>>(W2, b2, out);
}

// round 15
// speedup vs baseline: 1.0433x; 1.0263x over previous
#include <cuda_runtime.h>
#include <string.h>

// Problem constants
namespace {
constexpr int B_  = 4;
constexpr int C_  = 128;
constexpr int N_  = 1024;
constexpr int KNN = 20;
constexpr int M_  = 4096;   // N*UP
constexpr int OC  = 512;    // edge-conv out channels
constexpr int CH  = 130;    // net channels after grid concat
constexpr int CF  = 32;     // f/g channels
constexpr int MID = 256;    // W1 out
constexpr int RO  = 128;    // W2 out
}
#define EPS_ 1e-5f
#define NEGINF_ -3.4e38f

// ---- packed f32x2 FMA with defined-behavior punning ----
__device__ __forceinline__ float2 ffma2(float2 a, float2 b, float2 c) {
    unsigned long long au, bu, cu, du;
    memcpy(&au, &a, 8);
    memcpy(&bu, &b, 8);
    memcpy(&cu, &c, 8);
    asm("fma.rn.f32x2 %0, %1, %2, %3;" : "=l"(du) : "l"(au), "l"(bu), "l"(cu));
    float2 d;
    memcpy(&d, &du, 8);
    return d;
}
__device__ __forceinline__ float2 pack2(float x) { return make_float2(x, x); }

// ---- scratch (device globals; no allocations allowed) ----
__device__ float d_sq   [B_*N_];
__device__ float d_negd [B_*N_*N_];
__device__ int   d_idx  [B_*N_*KNN];
__device__ float d_Yt   [B_*N_*OC];    // [b][n][o]
__device__ float d_baset[B_*N_*OC];    // [b][n][o]
__device__ float d_st1p [2*256*OC];    // per-block partial sums (deterministic)
__device__ float d_st1  [2*OC];        // finalized: sc[o], sh[o]
__device__ float d_net3 [B_*CH*M_];    // [b][c][m]
__device__ float d_fr   [B_*CF*M_];
__device__ float d_gr   [B_*CF*M_];
__device__ float d_hr   [B_*CH*M_];
__device__ float d_st2  [2*(CF+CF+CH)];
__device__ float d_fn   [B_*CF*M_];
__device__ float d_gn   [B_*CF*M_];
__device__ float d_hn   [B_*CH*M_];
__device__ float d_s    [(size_t)B_*M_*M_];   // raw attention scores (never normalized)
__device__ float d_mxp  [(size_t)B_*M_*32];   // per (row, n-block) partial max
__device__ float d_zp   [(size_t)B_*M_*32];   // per (row, n-block) partial expsum
__device__ float d_mx   [B_*M_];              // per-row max
__device__ float d_wj   [B_*M_];              // gamma / Z per row
__device__ float d_n4   [B_*CH*M_];
__device__ float d_y1   [B_*MID*M_];

// ---------------- 1) per-point squared norms ----------------
__global__ void k_sq(const float* __restrict__ x) {
    int t = blockIdx.x * 256 + threadIdx.x;      // B*N = 4096
    int b = t >> 10, n = t & 1023;
    const float* xb = x + b * C_ * N_ + n;
    float s = 0.f;
#pragma unroll 8
    for (int c = 0; c < C_; c++) { float v = xb[c * N_]; s = fmaf(v, v, s); }
    d_sq[t] = s;
}

// ---------------- 2) neg squared distance: 2 x^T x - sq_n - sq_m ----------------
__global__ void k_negd(const float* __restrict__ x) {
    int b = blockIdx.z;
    int n0 = blockIdx.y * 64, m0 = blockIdx.x * 64;
    __shared__ float As[32][64];
    __shared__ float Bs[32][64];
    int tid = threadIdx.x;
    const float* xb = x + b * C_ * N_;
    float2 acc[4][2] = {};
    for (int k0 = 0; k0 < C_; k0 += 32) {
        for (int e = tid; e < 32 * 64; e += 256) {
            int k = e >> 6, i = e & 63;
            As[k][i] = xb[(k0 + k) * N_ + n0 + i];
            Bs[k][i] = xb[(k0 + k) * N_ + m0 + i];
        }
        __syncthreads();
        int ty = tid >> 4, tx = tid & 15;
#pragma unroll
        for (int k = 0; k < 32; k++) {
            float2 b0 = *(const float2*)&Bs[k][tx * 4];
            float2 b1 = *(const float2*)&Bs[k][tx * 4 + 2];
#pragma unroll
            for (int i = 0; i < 4; i++) {
                float2 av = pack2(As[k][ty * 4 + i]);
                acc[i][0] = ffma2(av, b0, acc[i][0]);
                acc[i][1] = ffma2(av, b1, acc[i][1]);
            }
        }
        __syncthreads();
    }
    int ty = tid >> 4, tx = tid & 15;
#pragma unroll
    for (int i = 0; i < 4; i++) {
        int n = n0 + ty * 4 + i;
        float sn = d_sq[b * N_ + n];
        float4 o;
        o.x = 2.f * acc[i][0].x - sn - d_sq[b * N_ + m0 + tx * 4 + 0];
        o.y = 2.f * acc[i][0].y - sn - d_sq[b * N_ + m0 + tx * 4 + 1];
        o.z = 2.f * acc[i][1].x - sn - d_sq[b * N_ + m0 + tx * 4 + 2];
        o.w = 2.f * acc[i][1].y - sn - d_sq[b * N_ + m0 + tx * 4 + 3];
        *(float4*)&d_negd[(b * N_ + n) * N_ + m0 + tx * 4] = o;
    }
}

// ---------------- 3) top-k (k=20), warp per row, tie -> lower index ----------------
__global__ void k_topk() {
    int row = blockIdx.x * 8 + (threadIdx.x >> 5);    // 4096 rows
    int lane = threadIdx.x & 31;
    const float* src = &d_negd[(size_t)row * N_];
    float v[32];
#pragma unroll
    for (int i = 0; i < 32; i++) v[i] = src[lane + i * 32];
    for (int t = 0; t < KNN; t++) {
        float bv = v[0]; int bi = lane;
#pragma unroll
        for (int i = 1; i < 32; i++) {
            int gi = i * 32 + lane;
            float vv = v[i];
            if (vv > bv || (vv == bv && gi < bi)) { bv = vv; bi = gi; }
        }
#pragma unroll
        for (int off = 16; off > 0; off >>= 1) {
            float ov = __shfl_down_sync(0xffffffff, bv, off);
            int   oi = __shfl_down_sync(0xffffffff, bi, off);
            if (ov > bv || (ov == bv && oi < bi)) { bv = ov; bi = oi; }
        }
        bi = __shfl_sync(0xffffffff, bi, 0);
        if (lane == 0) d_idx[row * KNN + t] = bi;
        int slot = bi >> 5;
        bool mine = (bi & 31) == lane;
#pragma unroll
        for (int i = 0; i < 32; i++) if (i == slot && mine) v[i] = NEGINF_;
    }
}

// ---------------- 4) Y = Wa@x, base = (Wb-Wa)@x, both point-major (coalesced Wec) ----------------
__global__ void k_yb(const float* __restrict__ x, const float* __restrict__ Wec) {
    int b = blockIdx.z;
    int n0 = blockIdx.y * 64;   // 16
    int o0 = blockIdx.x * 64;   // 8
    __shared__ float Xs[32][66];
    __shared__ float Was[32][66];
    __shared__ float Wbs[32][66];
    int tid = threadIdx.x;
    float2 a1[4][2] = {}, a2[4][2] = {};
    for (int k0 = 0; k0 < C_; k0 += 32) {
        for (int e = tid; e < 32 * 64; e += 256) {
            int k = e >> 6, i = e & 63;
            Xs[k][i] = x[b * C_ * N_ + (k0 + k) * N_ + n0 + i];
        }
        for (int e = tid; e < 64 * 32; e += 256) {
            int i = e >> 5, k = e & 31;
            float wa = Wec[(o0 + i) * 256 + k0 + k];
            float wb = Wec[(o0 + i) * 256 + 128 + k0 + k];
            Was[k][i] = wa;
            Wbs[k][i] = wb - wa;
        }
        __syncthreads();
        int ty = tid >> 4, tx = tid & 15;   // ty -> n, tx -> o
#pragma unroll
        for (int k = 0; k < 32; k++) {
            float2 wa0 = *(const float2*)&Was[k][tx * 4];
            float2 wa1 = *(const float2*)&Was[k][tx * 4 + 2];
            float2 wb0 = *(const float2*)&Wbs[k][tx * 4];
            float2 wb1 = *(const float2*)&Wbs[k][tx * 4 + 2];
#pragma unroll
            for (int i = 0; i < 4; i++) {
                float2 xv = pack2(Xs[k][ty * 4 + i]);
                a1[i][0] = ffma2(xv, wa0, a1[i][0]);
                a1[i][1] = ffma2(xv, wa1, a1[i][1]);
                a2[i][0] = ffma2(xv, wb0, a2[i][0]);
                a2[i][1] = ffma2(xv, wb1, a2[i][1]);
            }
        }
        __syncthreads();
    }
    int ty = tid >> 4, tx = tid & 15;
#pragma unroll
    for (int i = 0; i < 4; i++) {
        int n = n0 + ty * 4 + i;
        *(float4*)&d_Yt   [(b * N_ + n) * OC + o0 + tx * 4] =
            make_float4(a1[i][0].x, a1[i][0].y, a1[i][1].x, a1[i][1].y);
        *(float4*)&d_baset[(b * N_ + n) * OC + o0 + tx * 4] =
            make_float4(a2[i][0].x, a2[i][0].y, a2[i][1].x, a2[i][1].y);
    }
}

// ---------------- 5) BN stats for edge-conv (deterministic partials, 256 blocks) ----------------
__global__ void k_stats1() {
    int b = blockIdx.y;
    int nc = blockIdx.x;            // 64 chunks of 16 points
    int p = b * 64 + nc;
    int o = threadIdx.x;            // 512
    __shared__ int sidx[16 * KNN];
    for (int e = threadIdx.x; e < 16 * KNN; e += 512)
        sidx[e] = d_idx[(b * N_ + nc * 16) * KNN + e];
    __syncthreads();
    float s = 0.f, ss = 0.f;
    for (int nn = 0; nn < 16; nn++) {
        int n = nc * 16 + nn;
        float bv = d_baset[(b * N_ + n) * OC + o];
#pragma unroll
        for (int k = 0; k < KNN; k++) {
            int j = sidx[nn * KNN + k];
            float v = d_Yt[(b * N_ + j) * OC + o] + bv;
            s += v; ss = fmaf(v, v, ss);
        }
    }
    d_st1p[p * OC + o] = s;
    d_st1p[(256 + p) * OC + o] = ss;
}

// reduce partials AND finalize BN scale/shift: d_st1[o]=sc, d_st1[OC+o]=sh
__global__ void k_red1(const float* __restrict__ g_ec, const float* __restrict__ b_ec) {
    int o = blockIdx.x * 256 + threadIdx.x;
    if (o >= OC) return;
    float s = 0.f, ss = 0.f;
    for (int p = 0; p < 256; p++) { s += d_st1p[p * OC + o]; ss += d_st1p[(256 + p) * OC + o]; }
    const float cnt = (float)(B_ * N_ * KNN);
    float mean = s / cnt;
    float var  = ss / cnt - mean * mean;
    float sc = rsqrtf(var + EPS_) * g_ec[o];
    d_st1[o] = sc;
    d_st1[OC + o] = b_ec[o] - mean * sc;
}

// ---------------- 6) normalize + leaky + max over k, write reshaped net3 ----------------
__global__ void k_edgemax() {
    int bn = blockIdx.x;
    int b = bn >> 10, n = bn & 1023;
    __shared__ int sidx[KNN];
    int tid = threadIdx.x;
    if (tid < KNN) sidx[tid] = d_idx[bn * KNN + tid];
    __syncthreads();
    for (int o = tid; o < OC; o += 256) {
        float sc = d_st1[o];
        float sh = d_st1[OC + o];
        float bv = d_baset[bn * OC + o];
        float best = NEGINF_;
#pragma unroll
        for (int k = 0; k < KNN; k++) {
            float v = d_Yt[(b * N_ + sidx[k]) * OC + o] + bv;
            v = fmaf(v, sc, sh);
            v = v > 0.f ? v : 0.2f * v;
            best = fmaxf(best, v);
        }
        int u = o >> 7, c = o & 127;
        d_net3[(b * CH + c) * M_ + n * 4 + u] = best;
    }
}

__global__ void k_grid() {
    int t = blockIdx.x * 256 + threadIdx.x;   // B*M = 16384
    int b = t >> 12, m = t & 4095;
    int gi = m >> 10;
    float gx = (gi < 2) ? -0.2f : 0.2f;
    float gy = (gi & 1) ? 0.2f : -0.2f;
    d_net3[(b * CH + 128) * M_ + m] = gx;
    d_net3[(b * CH + 129) * M_ + m] = gy;
}

// ---------------- 7) f/g/h raw convs (K=130), q-split row assignment ----------------
__global__ void k_fgh(const float* __restrict__ Wf, const float* __restrict__ bf,
                      const float* __restrict__ Wg, const float* __restrict__ bg,
                      const float* __restrict__ Wh, const float* __restrict__ bh) {
    int b = blockIdx.y, m0 = blockIdx.x * 64, half = blockIdx.z;
    __shared__ float In[CH][64];
    int tid = threadIdx.x;
    for (int e = tid; e < CH * 64; e += 256) {
        int k = e >> 6, i = e & 63;
        In[k][i] = d_net3[(b * CH + k) * M_ + m0 + i];
    }
    __syncthreads();
    int mi = tid & 15, ri = tid >> 4;
    int rbase = half * 112 + ri;
    const float* wp[7]; float bs_[7]; float* op[7]; bool val[7];
#pragma unroll
    for (int q = 0; q < 7; q++) {
        int r = rbase + 16 * q;
        val[q] = (r < 194);
        if (!val[q]) { wp[q] = Wf; bs_[q] = 0.f; op[q] = d_fr; continue; }
        if (r < 32)      { wp[q] = Wf + r * CH;          bs_[q] = bf[r];      op[q] = &d_fr[(b * CF + r) * M_]; }
        else if (r < 64) { int c = r - 32; wp[q] = Wg + c * CH; bs_[q] = bg[c]; op[q] = &d_gr[(b * CF + c) * M_]; }
        else             { int c = r - 64; wp[q] = Wh + c * CH; bs_[q] = bh[c]; op[q] = &d_hr[(b * CH + c) * M_]; }
    }
    float acc[7][4] = {};
#pragma unroll 2
    for (int k = 0; k < CH; k++) {
        float4 iv = *(const float4*)&In[k][mi * 4];
#pragma unroll
        for (int q = 0; q < 7; q++) {
            float w = wp[q][k];
            acc[q][0] = fmaf(w, iv.x, acc[q][0]);
            acc[q][1] = fmaf(w, iv.y, acc[q][1]);
            acc[q][2] = fmaf(w, iv.z, acc[q][2]);
            acc[q][3] = fmaf(w, iv.w, acc[q][3]);
        }
    }
#pragma unroll
    for (int q = 0; q < 7; q++) {
        if (val[q]) {
            float bv = bs_[q];
            *(float4*)&op[q][m0 + mi * 4] =
                make_float4(acc[q][0] + bv, acc[q][1] + bv, acc[q][2] + bv, acc[q][3] + bv);
        }
    }
}

// ---------------- 8) BN stats for f/g/h (one block per channel) ----------------
__global__ void k_stats2() {
    int ch = blockIdx.x, tid = threadIdx.x;   // 194 channels
    __shared__ float r1[256], r2[256];
    float s = 0.f, ss = 0.f;
    for (int b = 0; b < B_; b++) {
        const float* p;
        if (ch < 32)      p = &d_fr[(b * CF + ch) * M_];
        else if (ch < 64) p = &d_gr[(b * CF + (ch - 32)) * M_];
        else              p = &d_hr[(b * CH + (ch - 64)) * M_];
        for (int m = tid; m < M_; m += 256) { float v = p[m]; s += v; ss = fmaf(v, v, ss); }
    }
    r1[tid] = s; r2[tid] = ss;
    __syncthreads();
    for (int st = 128; st > 0; st >>= 1) {
        if (tid < st) { r1[tid] += r1[tid + st]; r2[tid] += r2[tid + st]; }
        __syncthreads();
    }
    if (tid == 0) { d_st2[ch] = r1[0]; d_st2[194 + ch] = r2[0]; }
}

// ---------------- 9) normalize + relu (sel: 0=f, 1=g, 2=h) ----------------
__global__ void k_norm2(int sel, const float* __restrict__ gamma, const float* __restrict__ beta) {
    int t = blockIdx.x * 256 + threadIdx.x;
    int Cdim = (sel == 2) ? CH : CF;
    int total = B_ * Cdim * M_;
    if (t >= total) return;
    int c = (t / M_) % Cdim;
    int off = (sel == 0) ? 0 : (sel == 1) ? 32 : 64;
    const float cntf = (float)(B_ * M_);
    float mean = d_st2[off + c] / cntf;
    float var  = d_st2[194 + off + c] / cntf - mean * mean;
    float sc = rsqrtf(var + EPS_) * gamma[c];
    float sh = beta[c] - mean * sc;
    const float* raw = (sel == 0) ? d_fr : (sel == 1) ? d_gr : d_hr;
    float* outp      = (sel == 0) ? d_fn : (sel == 1) ? d_gn : d_hn;
    outp[t] = fmaxf(fmaf(raw[t], sc, sh), 0.f);
}

// ---------------- 10) s-GEMM + flash partials (per-row max & expsum of each 128-col tile) ----------------
__global__ void k_sgemm() {
    int b = blockIdx.z;
    int m0 = blockIdx.y * 64, n0 = blockIdx.x * 128;
    __shared__ float Gs[CF][64];
    __shared__ float Fs[CF][128];
    int tid = threadIdx.x;
    for (int e = tid; e < CF * 64; e += 256) {
        int k = e >> 6, i = e & 63;
        Gs[k][i] = d_gn[(b * CF + k) * M_ + m0 + i];
    }
    for (int e = tid; e < CF * 128; e += 256) {
        int k = e >> 7, i = e & 127;
        Fs[k][i] = d_fn[(b * CF + k) * M_ + n0 + i];
    }
    __syncthreads();
    int ty = tid >> 4, tx = tid & 15;   // ty -> m group (4), tx -> n group (8)
    float2 acc[4][4] = {};
#pragma unroll
    for (int k = 0; k < CF; k++) {
        float4 gv = *(const float4*)&Gs[k][ty * 4];
        float4 fa = *(const float4*)&Fs[k][tx * 8];
        float4 fb = *(const float4*)&Fs[k][tx * 8 + 4];
        float gm[4] = {gv.x, gv.y, gv.z, gv.w};
        float2 fn0 = make_float2(fa.x, fa.y), fn1 = make_float2(fa.z, fa.w);
        float2 fn2 = make_float2(fb.x, fb.y), fn3 = make_float2(fb.z, fb.w);
#pragma unroll
        for (int i = 0; i < 4; i++) {
            float2 gp = pack2(gm[i]);
            acc[i][0] = ffma2(gp, fn0, acc[i][0]);
            acc[i][1] = ffma2(gp, fn1, acc[i][1]);
            acc[i][2] = ffma2(gp, fn2, acc[i][2]);
            acc[i][3] = ffma2(gp, fn3, acc[i][3]);
        }
    }
#pragma unroll
    for (int i = 0; i < 4; i++) {
        int m = m0 + ty * 4 + i;
        float* dst = &d_s[((size_t)(b * M_ + m)) * M_ + n0 + tx * 8];
        *(float4*)&dst[0] = make_float4(acc[i][0].x, acc[i][0].y, acc[i][1].x, acc[i][1].y);
        *(float4*)&dst[4] = make_float4(acc[i][2].x, acc[i][2].y, acc[i][3].x, acc[i][3].y);
    }
    // ---- flash partials over this block's 128 cols (reuse smem as scratch) ----
    __syncthreads();
    float* RedM   = &Gs[0][0];    // [64][16]
    float* RedZ   = &Gs[16][0];   // [64][16]
    float* RowMax = &Fs[0][0];    // [64]
#pragma unroll
    for (int i = 0; i < 4; i++) {
        int r = ty * 4 + i;
        float lm = fmaxf(fmaxf(fmaxf(acc[i][0].x, acc[i][0].y), fmaxf(acc[i][1].x, acc[i][1].y)),
                         fmaxf(fmaxf(acc[i][2].x, acc[i][2].y), fmaxf(acc[i][3].x, acc[i][3].y)));
        RedM[r * 16 + tx] = lm;
    }
    __syncthreads();
    if (tid < 64) {
        float m = RedM[tid * 16];
#pragma unroll
        for (int t = 1; t < 16; t++) m = fmaxf(m, RedM[tid * 16 + t]);
        RowMax[tid] = m;
    }
    __syncthreads();
#pragma unroll
    for (int i = 0; i < 4; i++) {
        int r = ty * 4 + i;
        float mr = RowMax[r];
        float z = (__expf(acc[i][0].x - mr) + __expf(acc[i][0].y - mr))
                + (__expf(acc[i][1].x - mr) + __expf(acc[i][1].y - mr))
                + (__expf(acc[i][2].x - mr) + __expf(acc[i][2].y - mr))
                + (__expf(acc[i][3].x - mr) + __expf(acc[i][3].y - mr));
        RedZ[r * 16 + tx] = z;
    }
    __syncthreads();
    if (tid < 64) {
        float z = 0.f;
#pragma unroll
        for (int t = 0; t < 16; t++) z += RedZ[tid * 16 + t];
        int m = m0 + tid;
        d_mxp[((size_t)(b * M_ + m)) * 32 + blockIdx.x] = RowMax[tid];
        d_zp [((size_t)(b * M_ + m)) * 32 + blockIdx.x] = z;
    }
}

// ---------------- 11) combine flash partials: mx, wj = gamma/Z (warp per row) ----------------
__global__ void k_redrow(const float* __restrict__ gam) {
    int row = blockIdx.x * 8 + (threadIdx.x >> 5);    // B*M = 16384 rows
    int lane = threadIdx.x & 31;
    float mp = d_mxp[(size_t)row * 32 + lane];
    float zp = d_zp [(size_t)row * 32 + lane];
    float m = mp;
#pragma unroll
    for (int off = 16; off > 0; off >>= 1)
        m = fmaxf(m, __shfl_xor_sync(0xffffffff, m, off));
    float z = zp * __expf(mp - m);
#pragma unroll
    for (int off = 16; off > 0; off >>= 1)
        z += __shfl_xor_sync(0xffffffff, z, off);
    if (lane == 0) {
        d_mx[row] = m;
        d_wj[row] = gam[0] / z;
    }
}

// ---------------- 11b) fold wj into h: d_hn[b][c][j] *= wj[b][j] ----------------
__global__ void k_hmul() {
    int t = blockIdx.x * 256 + threadIdx.x;
    if (t >= B_ * CH * M_) return;
    int m = t % M_;
    int b = t / (CH * M_);
    d_hn[t] *= d_wj[b * M_ + m];
}

// ---------------- 12) n4 = sum_j hn[c,j]·exp(s[j,m]-mx_j) + net3  (k-tile 32) ----------------
__global__ void k_ogemm() {
    int b = blockIdx.y;
    int m0 = blockIdx.x * 64;
    __shared__ float Bs[32][64];
    __shared__ float Hs[32][144];
    int tid = threadIdx.x;
    int mi = tid & 15, ci = tid >> 4;   // m = m0+mi*4.., c-pairs ci*8+2cp; ci==0 also c=128,129
    float2 acc[4][4] = {};   // [cpair][m]
    float2 ace[4] = {};      // ci==0: (o[128,m], o[129,m])
    for (int j0 = 0; j0 < M_; j0 += 32) {
        // stage exp'd s tile: 32 x 64 (2 float4 per thread)
        for (int e = tid; e < 32 * 16; e += 256) {
            int k = e >> 4, c4 = e & 15;
            float4 v = *(const float4*)&d_s[((size_t)(b * M_ + j0 + k)) * M_ + m0 + c4 * 4];
            float mxv = d_mx[b * M_ + j0 + k];
            float4 p;
            p.x = __expf(v.x - mxv); p.y = __expf(v.y - mxv);
            p.z = __expf(v.z - mxv); p.w = __expf(v.w - mxv);
            *(float4*)&Bs[k][c4 * 4] = p;
        }
        // stage h (gamma/Z already folded): 32 x 144
        for (int e = tid; e < 32 * 144; e += 256) {
            int c = e >> 5, k = e & 31;
            Hs[k][c] = (c < CH) ? d_hn[(b * CH + c) * M_ + j0 + k] : 0.f;
        }
        __syncthreads();
#pragma unroll
        for (int k = 0; k < 32; k++) {
            float4 bv = *(const float4*)&Bs[k][mi * 4];
            float2 pm0 = pack2(bv.x), pm1 = pack2(bv.y), pm2 = pack2(bv.z), pm3 = pack2(bv.w);
            float4 h0 = *(const float4*)&Hs[k][ci * 8];
            float4 h1 = *(const float4*)&Hs[k][ci * 8 + 4];
            float2 hp0 = make_float2(h0.x, h0.y), hp1 = make_float2(h0.z, h0.w);
            float2 hp2 = make_float2(h1.x, h1.y), hp3 = make_float2(h1.z, h1.w);
            acc[0][0] = ffma2(hp0, pm0, acc[0][0]); acc[0][1] = ffma2(hp0, pm1, acc[0][1]);
            acc[0][2] = ffma2(hp0, pm2, acc[0][2]); acc[0][3] = ffma2(hp0, pm3, acc[0][3]);
            acc[1][0] = ffma2(hp1, pm0, acc[1][0]); acc[1][1] = ffma2(hp1, pm1, acc[1][1]);
            acc[1][2] = ffma2(hp1, pm2, acc[1][2]); acc[1][3] = ffma2(hp1, pm3, acc[1][3]);
            acc[2][0] = ffma2(hp2, pm0, acc[2][0]); acc[2][1] = ffma2(hp2, pm1, acc[2][1]);
            acc[2][2] = ffma2(hp2, pm2, acc[2][2]); acc[2][3] = ffma2(hp2, pm3, acc[2][3]);
            acc[3][0] = ffma2(hp3, pm0, acc[3][0]); acc[3][1] = ffma2(hp3, pm1, acc[3][1]);
            acc[3][2] = ffma2(hp3, pm2, acc[3][2]); acc[3][3] = ffma2(hp3, pm3, acc[3][3]);
            if (ci == 0) {
                float2 he = *(const float2*)&Hs[k][128];
                ace[0] = ffma2(he, pm0, ace[0]); ace[1] = ffma2(he, pm1, ace[1]);
                ace[2] = ffma2(he, pm2, ace[2]); ace[3] = ffma2(he, pm3, ace[3]);
            }
        }
        __syncthreads();
    }
#pragma unroll
    for (int cp = 0; cp < 4; cp++) {
        int c0 = ci * 8 + 2 * cp, c1 = c0 + 1;
        float4 va = *(const float4*)&d_net3[(b * CH + c0) * M_ + m0 + mi * 4];
        float4 vb = *(const float4*)&d_net3[(b * CH + c1) * M_ + m0 + mi * 4];
        *(float4*)&d_n4[(b * CH + c0) * M_ + m0 + mi * 4] = make_float4(
            acc[cp][0].x + va.x, acc[cp][1].x + va.y, acc[cp][2].x + va.z, acc[cp][3].x + va.w);
        *(float4*)&d_n4[(b * CH + c1) * M_ + m0 + mi * 4] = make_float4(
            acc[cp][0].y + vb.x, acc[cp][1].y + vb.y, acc[cp][2].y + vb.z, acc[cp][3].y + vb.w);
    }
    if (ci == 0) {
        float4 va = *(const float4*)&d_net3[(b * CH + 128) * M_ + m0 + mi * 4];
        float4 vb = *(const float4*)&d_net3[(b * CH + 129) * M_ + m0 + mi * 4];
        *(float4*)&d_n4[(b * CH + 128) * M_ + m0 + mi * 4] = make_float4(
            ace[0].x + va.x, ace[1].x + va.y, ace[2].x + va.z, ace[3].x + va.w);
        *(float4*)&d_n4[(b * CH + 129) * M_ + m0 + mi * 4] = make_float4(
            ace[0].y + vb.x, ace[1].y + vb.y, ace[2].y + vb.z, ace[3].y + vb.w);
    }
}

// ---------------- 14) y1 = relu(W1 @ net4 + b1)   (256x130), q-split ----------------
__global__ void k_mlp1(const float* __restrict__ W, const float* __restrict__ bias) {
    int b = blockIdx.y, m0 = blockIdx.x * 64, half = blockIdx.z;
    __shared__ float In[CH][64];
    int tid = threadIdx.x;
    for (int e = tid; e < CH * 64; e += 256) {
        int k = e >> 6, i = e & 63;
        In[k][i] = d_n4[(b * CH + k) * M_ + m0 + i];
    }
    __syncthreads();
    int mi = tid & 15, ri = tid >> 4;
    int rbase = half * 128 + ri;
    const float* wp[8];
#pragma unroll
    for (int q = 0; q < 8; q++) wp[q] = W + (rbase + 16 * q) * CH;
    float acc[8][4] = {};
#pragma unroll 2
    for (int k = 0; k < CH; k++) {
        float4 iv = *(const float4*)&In[k][mi * 4];
#pragma unroll
        for (int q = 0; q < 8; q++) {
            float w = wp[q][k];
            acc[q][0] = fmaf(w, iv.x, acc[q][0]);
            acc[q][1] = fmaf(w, iv.y, acc[q][1]);
            acc[q][2] = fmaf(w, iv.z, acc[q][2]);
            acc[q][3] = fmaf(w, iv.w, acc[q][3]);
        }
    }
#pragma unroll
    for (int q = 0; q < 8; q++) {
        int r = rbase + 16 * q;
        float bv = bias[r];
        *(float4*)&d_y1[((size_t)b * MID + r) * M_ + m0 + mi * 4] =
            make_float4(fmaxf(acc[q][0] + bv, 0.f), fmaxf(acc[q][1] + bv, 0.f),
                        fmaxf(acc[q][2] + bv, 0.f), fmaxf(acc[q][3] + bv, 0.f));
    }
}

// ---------------- 15) out = relu(W2 @ y1 + b2)   (128x256), q-split ----------------
__global__ void k_mlp2(const float* __restrict__ W, const float* __restrict__ bias,
                       float* __restrict__ Out) {
    int b = blockIdx.y, m0 = blockIdx.x * 32;
    __shared__ float In[MID][32];
    int tid = threadIdx.x;
    for (int e = tid; e < MID * 32; e += 256) {
        int k = e >> 5, i = e & 31;
        In[k][i] = d_y1[((size_t)b * MID + k) * M_ + m0 + i];
    }
    __syncthreads();
    int mi = tid & 7, ri = tid >> 3;     // 8 m-groups (32 m), 32 r-groups
    const float* wp[4];
#pragma unroll
    for (int q = 0; q < 4; q++) wp[q] = W + (ri + 32 * q) * MID;
    float acc[4][4] = {};
#pragma unroll 4
    for (int k = 0; k < MID; k++) {
        float4 iv = *(const float4*)&In[k][mi * 4];
#pragma unroll
        for (int q = 0; q < 4; q++) {
            float w = wp[q][k];
            acc[q][0] = fmaf(w, iv.x, acc[q][0]);
            acc[q][1] = fmaf(w, iv.y, acc[q][1]);
            acc[q][2] = fmaf(w, iv.z, acc[q][2]);
            acc[q][3] = fmaf(w, iv.w, acc[q][3]);
        }
    }
#pragma unroll
    for (int q = 0; q < 4; q++) {
        int r = ri + 32 * q;
        float bv = bias[r];
        *(float4*)&Out[((size_t)b * RO + r) * M_ + m0 + mi * 4] =
            make_float4(fmaxf(acc[q][0] + bv, 0.f), fmaxf(acc[q][1] + bv, 0.f),
                        fmaxf(acc[q][2] + bv, 0.f), fmaxf(acc[q][3] + bv, 0.f));
    }
}

// ---------------- launch ----------------
extern "C" void kernel_launch(void* const* d_in, const int* in_sizes, int n_in,
                              void* d_out, int out_size) {
    const float* x    = (const float*)d_in[0];
    const float* Wec  = (const float*)d_in[1];
    const float* g_ec = (const float*)d_in[2];
    const float* b_ec = (const float*)d_in[3];
    const float* Wf   = (const float*)d_in[4];
    const float* bf   = (const float*)d_in[5];
    const float* gf   = (const float*)d_in[6];
    const float* betf = (const float*)d_in[7];
    const float* Wg   = (const float*)d_in[8];
    const float* bg   = (const float*)d_in[9];
    const float* gg   = (const float*)d_in[10];
    const float* betg = (const float*)d_in[11];
    const float* Wh   = (const float*)d_in[12];
    const float* bh   = (const float*)d_in[13];
    const float* gh   = (const float*)d_in[14];
    const float* beth = (const float*)d_in[15];
    const float* gam  = (const float*)d_in[16];
    const float* W1   = (const float*)d_in[17];
    const float* b1   = (const float*)d_in[18];
    const float* W2   = (const float*)d_in[19];
    const float* b2   = (const float*)d_in[20];
    float* out = (float*)d_out;

    k_sq    <<<16, 256>>>(x);
    k_negd  <<<dim3(16, 16, 4), 256>>>(x);
    k_topk  <<<512, 256>>>();
    k_yb    <<<dim3(8, 16, 4), 256>>>(x, Wec);
    k_stats1<<<dim3(64, 4), 512>>>();
    k_red1  <<<2, 256>>>(g_ec, b_ec);
    k_edgemax<<<B_ * N_, 256>>>();
    k_grid  <<<64, 256>>>();
    k_fgh   <<<dim3(64, 4, 2), 256>>>(Wf, bf, Wg, bg, Wh, bh);
    k_stats2<<<194, 256>>>();
    k_norm2 <<<(B_ * CF * M_ + 255) / 256, 256>>>(0, gf, betf);
    k_norm2 <<<(B_ * CF * M_ + 255) / 256, 256>>>(1, gg, betg);
    k_norm2 <<<(B_ * CH * M_ + 255) / 256, 256>>>(2, gh, beth);
    k_sgemm <<<dim3(32, 64, 4), 256>>>();
    k_redrow<<<2048, 256>>>(gam);
    k_hmul  <<<(B_ * CH * M_ + 255) / 256, 256>>>();
    k_ogemm <<<dim3(64, 4), 256>>>();
    k_mlp1  <<<dim3(64, 4, 2), 256>>>(W1, b1);
    k_mlp2  <<<dim3(128, 4), 256>>>(W2, b2, out);
}